// round 15
// baseline (speedup 1.0000x reference)
#include <cuda_runtime.h>
#include <cuda_fp16.h>

#define T_STEPS 200
#define NIN     5
#define H       32
#define G4      128
#define NB      16            // batches per warp (2 n-tiles)
#define WARPS   4
#define THREADS (WARPS * 32)

#define WPITCH  56
#define HPITCH  48
#define HWARPSZ (48 * HPITCH)

#define SW_SCALE 718.4163f            // 127*sqrt(32)
#define INV_SCALE 1.0960e-5f          // 1/(SW_SCALE*127)

struct SmemLayout {
    __half Whi[G4][WPITCH];           // f16 W (g-gate rows used for pinning)
    __half Wx[G4][8];                 // x-part: 5 W_ih + bias + 0,0
    char   Ws8[G4][32];               // int8 W_hh (i,f,o rows used)
    __half Hbuf[WARPS][48][HPITCH/2]; // f16 h rows 0-31, x rows 32-36, ones 37
    char   Hs8[WARPS][16][32];        // s8 h: [batch col][unit]
};

// ---------- PTX helpers ----------
__device__ __forceinline__ unsigned smem_u32(const void* p) {
    unsigned a;
    asm("{ .reg .u64 t; cvta.to.shared.u64 t, %1; cvt.u32.u64 %0, t; }"
        : "=r"(a) : "l"(p));
    return a;
}
__device__ __forceinline__ void ldsm_x4(unsigned& a0, unsigned& a1,
                                        unsigned& a2, unsigned& a3, unsigned addr) {
    asm volatile("ldmatrix.sync.aligned.m8n8.x4.shared.b16 {%0,%1,%2,%3}, [%4];"
                 : "=r"(a0), "=r"(a1), "=r"(a2), "=r"(a3) : "r"(addr));
}
__device__ __forceinline__ void ldsm_x2(unsigned& a0, unsigned& a1, unsigned addr) {
    asm volatile("ldmatrix.sync.aligned.m8n8.x2.shared.b16 {%0,%1}, [%2];"
                 : "=r"(a0), "=r"(a1) : "r"(addr));
}
__device__ __forceinline__ void ldsm_x4t(unsigned& b0, unsigned& b1,
                                         unsigned& b2, unsigned& b3, unsigned addr) {
    asm volatile("ldmatrix.sync.aligned.m8n8.x4.trans.shared.b16 {%0,%1,%2,%3}, [%4];"
                 : "=r"(b0), "=r"(b1), "=r"(b2), "=r"(b3) : "r"(addr));
}
__device__ __forceinline__ void ldsm_x2t(unsigned& b0, unsigned& b1, unsigned addr) {
    asm volatile("ldmatrix.sync.aligned.m8n8.x2.trans.shared.b16 {%0,%1}, [%2];"
                 : "=r"(b0), "=r"(b1) : "r"(addr));
}
#define MMA(Cr, A0, A1, A2, A3, B0, B1)                                        \
    asm volatile("mma.sync.aligned.m16n8k16.row.col.f32.f16.f16.f32 "          \
                 "{%0,%1,%2,%3}, {%4,%5,%6,%7}, {%8,%9}, {%0,%1,%2,%3};"       \
                 : "+f"((Cr)[0]), "+f"((Cr)[1]), "+f"((Cr)[2]), "+f"((Cr)[3])  \
                 : "r"(A0), "r"(A1), "r"(A2), "r"(A3), "r"(B0), "r"(B1))
#define MMA8(Cr, A0, A1, B0)                                                   \
    asm volatile("mma.sync.aligned.m16n8k8.row.col.f32.f16.f16.f32 "           \
                 "{%0,%1,%2,%3}, {%4,%5}, {%6}, {%0,%1,%2,%3};"                \
                 : "+f"((Cr)[0]), "+f"((Cr)[1]), "+f"((Cr)[2]), "+f"((Cr)[3])  \
                 : "r"(A0), "r"(A1), "r"(B0))
#define IMMA(Sr, A0, A1, A2, A3, B0, B1)                                       \
    asm volatile("mma.sync.aligned.m16n8k32.row.col.s32.s8.s8.s32 "            \
                 "{%0,%1,%2,%3}, {%4,%5,%6,%7}, {%8,%9}, {%0,%1,%2,%3};"       \
                 : "+r"((Sr)[0]), "+r"((Sr)[1]), "+r"((Sr)[2]), "+r"((Sr)[3])  \
                 : "r"(A0), "r"(A1), "r"(A2), "r"(A3), "r"(B0), "r"(B1))

__device__ __forceinline__ void sts32(unsigned addr, unsigned v) {
    asm volatile("st.shared.b32 [%0], %1;" :: "r"(addr), "r"(v) : "memory");
}
__device__ __forceinline__ void sts16(unsigned addr, unsigned short v) {
    asm volatile("st.shared.b16 [%0], %1;" :: "r"(addr), "h"(v) : "memory");
}
__device__ __forceinline__ void sts8(unsigned addr, int v) {
    asm volatile("st.shared.b8 [%0], %1;" :: "r"(addr), "r"(v) : "memory");
}
__device__ __forceinline__ unsigned lds32(unsigned addr) {
    unsigned v;
    asm volatile("ld.shared.b32 %0, [%1];" : "=r"(v) : "r"(addr) : "memory");
    return v;
}

// ---------- packed f16x2 helpers ----------
__device__ __forceinline__ __half2 tanh2(__half2 v) {
    unsigned u = *reinterpret_cast<unsigned*>(&v), r;
    asm("tanh.approx.f16x2 %0, %1;" : "=r"(r) : "r"(u));
    return *reinterpret_cast<__half2*>(&r);
}
__device__ __forceinline__ __half2 pack2h(float e0, float e1) {   // low=e0
    unsigned r;
    asm("cvt.rn.f16x2.f32 %0, %1, %2;" : "=r"(r) : "f"(e1), "f"(e0));
    return *reinterpret_cast<__half2*>(&r);
}
__device__ __forceinline__ unsigned h2bits(__half2 v) {
    return *reinterpret_cast<unsigned*>(&v);
}
__device__ __forceinline__ __half2 bits2h(unsigned u) {
    return *reinterpret_cast<__half2*>(&u);
}
__device__ __forceinline__ int f16_to_s32_rni(__half h) {
    int r;
    unsigned short hb = *reinterpret_cast<unsigned short*>(&h);
    asm("cvt.rni.s32.f16 %0, %1;" : "=r"(r) : "h"(hb));
    return r;
}

__global__ void __launch_bounds__(THREADS, 2)
lstm_imma_kernel(const float* __restrict__ x,
                 const float* __restrict__ W_ih,
                 const float* __restrict__ W_hh,
                 const float* __restrict__ b_ih,
                 const float* __restrict__ b_hh,
                 const float* __restrict__ W_fc,
                 const float* __restrict__ b_fc,
                 float* __restrict__ out, int B) {
    __shared__ __align__(16) SmemLayout sm;

    const int tid  = threadIdx.x;
    const int wid  = tid >> 5;
    const int lane = tid & 31;

    // ============ init ============
    if (tid < G4) {
        const int g = tid;
        for (int k = 0; k < WPITCH; ++k) {
            float v = (k < H) ? W_hh[g * H + k] : 0.0f;
            sm.Whi[g][k] = __float2half(v);
        }
        for (int d = 0; d < NIN; ++d) sm.Wx[g][d] = __float2half(W_ih[g * NIN + d]);
        sm.Wx[g][5] = __float2half(b_ih[g] + b_hh[g]);
        sm.Wx[g][6] = __float2half(0.0f);
        sm.Wx[g][7] = __float2half(0.0f);
        for (int k = 0; k < H; ++k)
            sm.Ws8[g][k] = (char)__float2int_rn(W_hh[g * H + k] * SW_SCALE);
    }
    {   // zero Hbuf + Hs8
        unsigned* hz = (unsigned*)&sm.Hbuf[0][0][0];
        for (int i = tid; i < (WARPS * HWARPSZ) / 4; i += THREADS) hz[i] = 0u;
        unsigned* sz = (unsigned*)&sm.Hs8[0][0][0];
        for (int i = tid; i < (WARPS * 16 * 32) / 4; i += THREADS) sz[i] = 0u;
    }
    __syncthreads();
    if (tid < WARPS * NB)
        sm.Hbuf[tid / NB][37][tid % NB] = __float2half(1.0f);
    __syncthreads();

    const int wb0 = blockIdx.x * (WARPS * NB) + wid * NB;
    if (wb0 >= B) return;

    const unsigned sbase   = smem_u32(&sm);
    const unsigned wxbase  = smem_u32(&sm.Wx[0][0]);
    const unsigned ws8base = smem_u32(&sm.Ws8[0][0]);
    const unsigned laneA   = (unsigned)((lane & 15) * (WPITCH * 2) + (lane >> 4) * 16);
    const unsigned hwarp   = smem_u32(&sm.Hbuf[wid][0][0]);
    const unsigned hs8warp = smem_u32(&sm.Hs8[wid][0][0]);
    const unsigned addrB   = hwarp + (unsigned)((lane & 15) * HPITCH + (lane >> 4) * 16);
    const int v15 = lane & 15;
    const unsigned addrBx  = hwarp + (unsigned)((32 + (v15 & 7)) * HPITCH + (v15 >> 3) * 16);
    const int gl = lane >> 2;
    const int tl = lane & 3;

    // ---- pin A fragments ----
    // g-gate f16 (mt 4,5; k16 x2)
    unsigned wg[2][2][4];
#pragma unroll
    for (int m = 0; m < 2; ++m)
#pragma unroll
        for (int kc = 0; kc < 2; ++kc)
            ldsm_x4(wg[m][kc][0], wg[m][kc][1], wg[m][kc][2], wg[m][kc][3],
                    sbase + laneA + (unsigned)((4 + m) * (16 * WPITCH * 2) + kc * 32));
    // x-part k8 (all 8 mt)
    unsigned wx[8][2];
#pragma unroll
    for (int mt = 0; mt < 8; ++mt)
        ldsm_x2(wx[mt][0], wx[mt][1],
                wxbase + (unsigned)((mt * 16 + (lane & 15)) * 16));
    // i,f,o int8 (mts 0,1,2,3,6,7): A frag via plain LDS
    const int immaMt[6] = {0, 1, 2, 3, 6, 7};
    unsigned ai[6][4];
#pragma unroll
    for (int j = 0; j < 6; ++j) {
        const unsigned rbase = ws8base + (unsigned)(immaMt[j] * 16 * 32);
        ai[j][0] = lds32(rbase + (unsigned)(gl * 32 + tl * 4));
        ai[j][1] = lds32(rbase + (unsigned)((gl + 8) * 32 + tl * 4));
        ai[j][2] = lds32(rbase + (unsigned)(gl * 32 + tl * 4 + 16));
        ai[j][3] = lds32(rbase + (unsigned)((gl + 8) * 32 + tl * 4 + 16));
    }

    const float* xr = x + (size_t)(wb0 + lane) * (T_STEPS * NIN);  // lane<16 valid

    float xv[NIN];
    if (lane < NB) {
#pragma unroll
        for (int d = 0; d < NIN; ++d) xv[d] = xr[d];
    }

    float creg[16];
    __half2 h2[8];
#pragma unroll
    for (int i = 0; i < 16; ++i) creg[i] = 0.0f;
#pragma unroll
    for (int i = 0; i < 8; ++i) h2[i] = bits2h(0u);

    const __half2 h05  = __float2half2_rn(0.5f);
    const __half2 h127 = __float2half2_rn(127.0f);

#pragma unroll 1
    for (int t = 0; t < T_STEPS; ++t) {
        // ---- write h f16 (for g-gate HMMA) ----
#pragma unroll
        for (int p = 0; p < 2; ++p)
#pragma unroll
            for (int rr = 0; rr < 2; ++rr) {
                const int u = p * 16 + rr * 8 + gl;
#pragma unroll
                for (int nt = 0; nt < 2; ++nt)
                    sts32(hwarp + (unsigned)(u * HPITCH + (nt * 8 + 2 * tl) * 2),
                          h2bits(h2[4 * p + 2 * rr + nt]));
            }
        // ---- write h s8 (for i,f,o IMMA): Hs8[col][u] ----
#pragma unroll
        for (int p = 0; p < 2; ++p)
#pragma unroll
            for (int rr = 0; rr < 2; ++rr) {
                const int u = p * 16 + rr * 8 + gl;
#pragma unroll
                for (int nt = 0; nt < 2; ++nt) {
                    __half2 hq = __hmul2(h2[4 * p + 2 * rr + nt], h127);
                    int q0 = f16_to_s32_rni(__low2half(hq));
                    int q1 = f16_to_s32_rni(__high2half(hq));
                    const int c0i = nt * 8 + 2 * tl;
                    sts8(hs8warp + (unsigned)(c0i * 32 + u), q0);
                    sts8(hs8warp + (unsigned)((c0i + 1) * 32 + u), q1);
                }
            }
        // ---- write x rows 32..36 (f16) ----
        if (lane < NB) {
#pragma unroll
            for (int d = 0; d < NIN; ++d) {
                __half xh = __float2half(xv[d]);
                sts16(hwarp + (unsigned)((32 + d) * HPITCH + lane * 2),
                      *reinterpret_cast<unsigned short*>(&xh));
            }
        }
        __syncwarp();

        // ---- prefetch next x ----
        if (t + 1 < T_STEPS && lane < NB) {
#pragma unroll
            for (int d = 0; d < NIN; ++d) xv[d] = xr[(t + 1) * NIN + d];
        }

        // ---- accumulators ----
        float Cacc[8][2][4];      // f32: x-part (all gates) + g h-part
        int   Sacc[6][2][4];      // s32: i,f,o h-part
#pragma unroll
        for (int m = 0; m < 8; ++m)
#pragma unroll
            for (int n = 0; n < 2; ++n)
#pragma unroll
                for (int e = 0; e < 4; ++e) Cacc[m][n][e] = 0.0f;
#pragma unroll
        for (int m = 0; m < 6; ++m)
#pragma unroll
            for (int n = 0; n < 2; ++n)
#pragma unroll
                for (int e = 0; e < 4; ++e) Sacc[m][n][e] = 0;

        // ---- IMMA: i,f,o h-part (one k32 chunk) ----
        {
            unsigned bs0[2], bs1[2];
#pragma unroll
            for (int nt = 0; nt < 2; ++nt) {
                const unsigned cb = hs8warp + (unsigned)((nt * 8 + gl) * 32 + tl * 4);
                bs0[nt] = lds32(cb);
                bs1[nt] = lds32(cb + 16);
            }
#pragma unroll
            for (int j = 0; j < 6; ++j) {
                IMMA(Sacc[j][0], ai[j][0], ai[j][1], ai[j][2], ai[j][3],
                     bs0[0], bs1[0]);
                IMMA(Sacc[j][1], ai[j][0], ai[j][1], ai[j][2], ai[j][3],
                     bs0[1], bs1[1]);
            }
        }
        // ---- g-gate f16 h-part (2 x k16) ----
#pragma unroll
        for (int kc = 0; kc < 2; ++kc) {
            unsigned rb0, rb1, rb2, rb3;
            ldsm_x4t(rb0, rb1, rb2, rb3, addrB + (unsigned)(kc * 16 * HPITCH));
#pragma unroll
            for (int m = 0; m < 2; ++m) {
                MMA(Cacc[4 + m][0], wg[m][kc][0], wg[m][kc][1],
                    wg[m][kc][2], wg[m][kc][3], rb0, rb1);
                MMA(Cacc[4 + m][1], wg[m][kc][0], wg[m][kc][1],
                    wg[m][kc][2], wg[m][kc][3], rb2, rb3);
            }
        }
        // ---- x + bias (k8, all gates, f32 acc) ----
        {
            unsigned bx0, bx1;
            ldsm_x2t(bx0, bx1, addrBx);
#pragma unroll
            for (int mt = 0; mt < 8; ++mt) {
                MMA8(Cacc[mt][0], wx[mt][0], wx[mt][1], bx0);
                MMA8(Cacc[mt][1], wx[mt][0], wx[mt][1], bx1);
            }
        }

        // ---- dequant i,f,o into Cacc ----
        // Sacc j: 0,1 -> i (mt0,1); 2,3 -> f (mt2,3); 4,5 -> o (mt6,7)
#pragma unroll
        for (int jp = 0; jp < 2; ++jp)
#pragma unroll
            for (int nt = 0; nt < 2; ++nt)
#pragma unroll
                for (int e = 0; e < 4; ++e) {
                    Cacc[jp][nt][e] =
                        fmaf((float)Sacc[jp][nt][e], INV_SCALE, Cacc[jp][nt][e]);
                    Cacc[2 + jp][nt][e] =
                        fmaf((float)Sacc[2 + jp][nt][e], INV_SCALE, Cacc[2 + jp][nt][e]);
                    Cacc[6 + jp][nt][e] =
                        fmaf((float)Sacc[4 + jp][nt][e], INV_SCALE, Cacc[6 + jp][nt][e]);
                }

        // ---- packed f16x2 activations + fp32 c update ----
#pragma unroll
        for (int p = 0; p < 2; ++p)
#pragma unroll
            for (int nt = 0; nt < 2; ++nt)
#pragma unroll
                for (int rr = 0; rr < 2; ++rr) {
                    const int j0 = rr * 2, j1 = rr * 2 + 1;
                    __half2 ci = pack2h(Cacc[p][nt][j0],     Cacc[p][nt][j1]);
                    __half2 cf = pack2h(Cacc[2 + p][nt][j0], Cacc[2 + p][nt][j1]);
                    __half2 cg = pack2h(Cacc[4 + p][nt][j0], Cacc[4 + p][nt][j1]);
                    __half2 co = pack2h(Cacc[6 + p][nt][j0], Cacc[6 + p][nt][j1]);
                    __half2 gi = __hfma2(tanh2(__hmul2(ci, h05)), h05, h05);
                    __half2 gf = __hfma2(tanh2(__hmul2(cf, h05)), h05, h05);
                    __half2 gg = tanh2(cg);
                    __half2 go = __hfma2(tanh2(__hmul2(co, h05)), h05, h05);
                    __half2 ig = __hmul2(gi, gg);
                    const int idx = 8 * p + 4 * rr + 2 * nt;
                    float c0 = fmaf(__low2float(gf),  creg[idx],     __low2float(ig));
                    float c1 = fmaf(__high2float(gf), creg[idx + 1], __high2float(ig));
                    creg[idx]     = c0;
                    creg[idx + 1] = c1;
                    __half2 tc = tanh2(pack2h(c0, c1));
                    h2[4 * p + 2 * rr + nt] = __hmul2(go, tc);
                }
    }

    // ============ final projection ============
    float acc[4][2];
#pragma unroll
    for (int q = 0; q < 4; ++q) { acc[q][0] = 0.0f; acc[q][1] = 0.0f; }
#pragma unroll
    for (int p = 0; p < 2; ++p)
#pragma unroll
        for (int rr = 0; rr < 2; ++rr) {
            const int u = p * 16 + rr * 8 + gl;
            const float w0 = W_fc[u], w1 = W_fc[H + u];
#pragma unroll
            for (int nt = 0; nt < 2; ++nt) {
                const __half2 hv = h2[4 * p + 2 * rr + nt];
                const float hv0 = __low2float(hv), hv1 = __high2float(hv);
                acc[nt * 2 + 0][0] = fmaf(hv0, w0, acc[nt * 2 + 0][0]);
                acc[nt * 2 + 0][1] = fmaf(hv0, w1, acc[nt * 2 + 0][1]);
                acc[nt * 2 + 1][0] = fmaf(hv1, w0, acc[nt * 2 + 1][0]);
                acc[nt * 2 + 1][1] = fmaf(hv1, w1, acc[nt * 2 + 1][1]);
            }
        }
#pragma unroll
    for (int off = 4; off <= 16; off <<= 1)
#pragma unroll
        for (int q = 0; q < 4; ++q) {
            acc[q][0] += __shfl_xor_sync(0xffffffffu, acc[q][0], off);
            acc[q][1] += __shfl_xor_sync(0xffffffffu, acc[q][1], off);
        }
    if (lane < 4) {
        const float f0 = b_fc[0], f1 = b_fc[1];
#pragma unroll
        for (int nt = 0; nt < 2; ++nt)
#pragma unroll
            for (int e = 0; e < 2; ++e) {
                const int col = nt * 8 + 2 * lane + e;
                out[(wb0 + col) * 2 + 0] = acc[nt * 2 + e][0] + f0;
                out[(wb0 + col) * 2 + 1] = acc[nt * 2 + e][1] + f1;
            }
    }
}

extern "C" void kernel_launch(void* const* d_in, const int* in_sizes, int n_in,
                              void* d_out, int out_size) {
    const float* x    = (const float*)d_in[0];
    const float* W_ih = (const float*)d_in[1];
    const float* W_hh = (const float*)d_in[2];
    const float* b_ih = (const float*)d_in[3];
    const float* b_hh = (const float*)d_in[4];
    const float* W_fc = (const float*)d_in[5];
    const float* b_fc = (const float*)d_in[6];
    float* out = (float*)d_out;

    int B = in_sizes[0] / (T_STEPS * NIN);
    int bpc = WARPS * NB;                      // 64 batches per CTA
    int blocks = (B + bpc - 1) / bpc;
    lstm_imma_kernel<<<blocks, THREADS>>>(x, W_ih, W_hh, b_ih, b_hh,
                                          W_fc, b_fc, out, B);
}

// round 16
// speedup vs baseline: 1.6869x; 1.6869x over previous
#include <cuda_runtime.h>
#include <cuda_fp16.h>

#define T_STEPS 200
#define NIN     5
#define H       32
#define G4      128
#define NB      16            // batches per warp (2 n-tiles)
#define WARPS   4
#define THREADS (WARPS * 32)

#define WPITCH  56                        // halfs per W row (112 B, LDSM conflict-free)
#define WBYTES  (G4 * WPITCH * 2)         // 14336
#define OFF_H   WBYTES
#define HPITCH  48                        // bytes per Hbuf row
#define HROWS   64                        // 0-31 h, 32-47 x-even, 48-63 x-odd
#define HWARPSZ (HROWS * HPITCH)          // 3072 per warp

struct SmemLayout {
    __half Whi[G4][WPITCH];
    __half Hbuf[WARPS][HROWS][HPITCH / 2];
};

// ---------- PTX helpers ----------
__device__ __forceinline__ unsigned smem_u32(const void* p) {
    unsigned a;
    asm("{ .reg .u64 t; cvta.to.shared.u64 t, %1; cvt.u32.u64 %0, t; }"
        : "=r"(a) : "l"(p));
    return a;
}
__device__ __forceinline__ void ldsm_x4(unsigned& a0, unsigned& a1,
                                        unsigned& a2, unsigned& a3, unsigned addr) {
    asm volatile("ldmatrix.sync.aligned.m8n8.x4.shared.b16 {%0,%1,%2,%3}, [%4];"
                 : "=r"(a0), "=r"(a1), "=r"(a2), "=r"(a3) : "r"(addr));
}
__device__ __forceinline__ void ldsm_x4t(unsigned& b0, unsigned& b1,
                                         unsigned& b2, unsigned& b3, unsigned addr) {
    asm volatile("ldmatrix.sync.aligned.m8n8.x4.trans.shared.b16 {%0,%1,%2,%3}, [%4];"
                 : "=r"(b0), "=r"(b1), "=r"(b2), "=r"(b3) : "r"(addr));
}
#define MMA(Cr, A0, A1, A2, A3, B0, B1)                                        \
    asm volatile("mma.sync.aligned.m16n8k16.row.col.f32.f16.f16.f32 "          \
                 "{%0,%1,%2,%3}, {%4,%5,%6,%7}, {%8,%9}, {%0,%1,%2,%3};"       \
                 : "+f"((Cr)[0]), "+f"((Cr)[1]), "+f"((Cr)[2]), "+f"((Cr)[3])  \
                 : "r"(A0), "r"(A1), "r"(A2), "r"(A3), "r"(B0), "r"(B1))

__device__ __forceinline__ void sts32(unsigned addr, unsigned v) {
    asm volatile("st.shared.b32 [%0], %1;" :: "r"(addr), "r"(v) : "memory");
}
__device__ __forceinline__ void sts16(unsigned addr, unsigned short v) {
    asm volatile("st.shared.b16 [%0], %1;" :: "r"(addr), "h"(v) : "memory");
}

// ---------- packed f16x2 helpers ----------
__device__ __forceinline__ __half2 tanh2(__half2 v) {
    unsigned u = *reinterpret_cast<unsigned*>(&v), r;
    asm("tanh.approx.f16x2 %0, %1;" : "=r"(r) : "r"(u));
    return *reinterpret_cast<__half2*>(&r);
}
__device__ __forceinline__ __half2 pack2h(float e0, float e1) {   // low=e0
    unsigned r;
    asm("cvt.rn.f16x2.f32 %0, %1, %2;" : "=r"(r) : "f"(e1), "f"(e0));
    return *reinterpret_cast<__half2*>(&r);
}
__device__ __forceinline__ unsigned h2bits(__half2 v) {
    return *reinterpret_cast<unsigned*>(&v);
}
__device__ __forceinline__ __half2 bits2h(unsigned u) {
    return *reinterpret_cast<__half2*>(&u);
}

__global__ void __launch_bounds__(THREADS, 2)
lstm_xdb_kernel(const float* __restrict__ x,
                const float* __restrict__ W_ih,
                const float* __restrict__ W_hh,
                const float* __restrict__ b_ih,
                const float* __restrict__ b_hh,
                const float* __restrict__ W_fc,
                const float* __restrict__ b_fc,
                float* __restrict__ out, int B) {
    __shared__ __align__(16) SmemLayout sm;

    const int tid  = threadIdx.x;
    const int wid  = tid >> 5;
    const int lane = tid & 31;

    // ============ init: W fp16 (x_lo duplicated cols) ============
    if (tid < G4) {
        const int g = tid;
        for (int k = 0; k < WPITCH; ++k) {
            float v;
            if (k < H)            v = W_hh[g * H + k];
            else if (k < 37)      v = W_ih[g * NIN + (k - 32)];
            else if (k == 37)     v = b_ih[g] + b_hh[g];
            else if (k >= 38 && k < 43) v = W_ih[g * NIN + (k - 38)];  // x_lo cols
            else                  v = 0.0f;
            sm.Whi[g][k] = __float2half(v);
        }
    }
    {   // zero H buffers (incl. both x blocks' padding rows)
        unsigned* hz = (unsigned*)&sm.Hbuf[0][0][0];
        for (int i = tid; i < (WARPS * HWARPSZ) / 4; i += THREADS) hz[i] = 0u;
    }
    __syncthreads();
    if (tid < WARPS * NB) {   // ones rows: 37 (even buf) and 53 (odd buf)
        sm.Hbuf[tid / NB][37][tid % NB] = __float2half(1.0f);
        sm.Hbuf[tid / NB][53][tid % NB] = __float2half(1.0f);
    }
    __syncthreads();

    const int wb0 = blockIdx.x * (WARPS * NB) + wid * NB;
    if (wb0 >= B) return;

    const unsigned sbase = smem_u32(&sm);
    const unsigned laneA = (unsigned)((lane & 15) * (WPITCH * 2) + (lane >> 4) * 16);
    const unsigned hwarp = sbase + OFF_H + wid * HWARPSZ;
    const unsigned bOff  = (unsigned)((lane & 15) * HPITCH + (lane >> 4) * 16);
    const unsigned addrB = hwarp + bOff;
    const int gl = lane >> 2;
    const int tl = lane & 3;

    // ---- pin W fragments in registers (step-invariant; kc2 shared by both x-bufs) ----
    unsigned wa[8][3][4];
#pragma unroll
    for (int mt = 0; mt < 8; ++mt)
#pragma unroll
        for (int kc = 0; kc < 3; ++kc)
            ldsm_x4(wa[mt][kc][0], wa[mt][kc][1], wa[mt][kc][2], wa[mt][kc][3],
                    sbase + laneA + (unsigned)(mt * (16 * WPITCH * 2) + kc * 32));

    const float* xr = x + (size_t)(wb0 + lane) * (T_STEPS * NIN);  // lane<16 valid

    // ---- stage x(0) into even buffer; preload xv = x(1) ----
    float xv[NIN];
    if (lane < NB) {
#pragma unroll
        for (int d = 0; d < NIN; ++d) {
            float v = xr[d];
            __half xh = __float2half(v);
            __half xl = __float2half(v - __half2float(xh));
            sts16(hwarp + (unsigned)((32 + d) * HPITCH + lane * 2),
                  *reinterpret_cast<unsigned short*>(&xh));
            sts16(hwarp + (unsigned)((38 + d) * HPITCH + lane * 2),
                  *reinterpret_cast<unsigned short*>(&xl));
        }
#pragma unroll
        for (int d = 0; d < NIN; ++d) xv[d] = xr[NIN + d];
    }
    __syncwarp();

    float creg[16];
    __half2 h2[8];
#pragma unroll
    for (int i = 0; i < 16; ++i) creg[i] = 0.0f;
#pragma unroll
    for (int i = 0; i < 8; ++i) h2[i] = bits2h(0u);

    const __half2 h05 = __float2half2_rn(0.5f);

#pragma unroll 2
    for (int t = 0; t < T_STEPS; ++t) {
        const unsigned xrow_cur = (unsigned)(32 + 16 * (t & 1));
        const unsigned xrow_nxt = (unsigned)(32 + 16 * ((t + 1) & 1));

        float Cacc[8][2][4];
#pragma unroll
        for (int m = 0; m < 8; ++m)
#pragma unroll
            for (int n = 0; n < 2; ++n)
#pragma unroll
                for (int e = 0; e < 4; ++e) Cacc[m][n][e] = 0.0f;

        // ---- (1) x-part MMAs FIRST: B pre-staged & pre-synced last iter ----
        {
            unsigned rb0, rb1, rb2, rb3;
            ldsm_x4t(rb0, rb1, rb2, rb3, addrB + xrow_cur * HPITCH);
#pragma unroll
            for (int mt = 0; mt < 8; ++mt) {
                MMA(Cacc[mt][0], wa[mt][2][0], wa[mt][2][1],
                    wa[mt][2][2], wa[mt][2][3], rb0, rb1);
                MMA(Cacc[mt][1], wa[mt][2][0], wa[mt][2][1],
                    wa[mt][2][2], wa[mt][2][3], rb2, rb3);
            }
        }

        // ---- (2) write h(t) + stage x(t+1) into alternate block ----
#pragma unroll
        for (int p = 0; p < 2; ++p)
#pragma unroll
            for (int rr = 0; rr < 2; ++rr) {
                const int u = p * 16 + rr * 8 + gl;
#pragma unroll
                for (int nt = 0; nt < 2; ++nt)
                    sts32(hwarp + (unsigned)(u * HPITCH + (nt * 8 + 2 * tl) * 2),
                          h2bits(h2[4 * p + 2 * rr + nt]));
            }
        if (t + 1 < T_STEPS && lane < NB) {
#pragma unroll
            for (int d = 0; d < NIN; ++d) {
                __half xh = __float2half(xv[d]);
                __half xl = __float2half(xv[d] - __half2float(xh));
                sts16(hwarp + (xrow_nxt + d) * HPITCH + (unsigned)(lane * 2),
                      *reinterpret_cast<unsigned short*>(&xh));
                sts16(hwarp + (xrow_nxt + 6 + d) * HPITCH + (unsigned)(lane * 2),
                      *reinterpret_cast<unsigned short*>(&xl));
            }
        }
        __syncwarp();

        // ---- (3) h-part MMAs ----
#pragma unroll
        for (int kc = 0; kc < 2; ++kc) {
            unsigned rb0, rb1, rb2, rb3;
            ldsm_x4t(rb0, rb1, rb2, rb3, addrB + (unsigned)(kc * 16 * HPITCH));
#pragma unroll
            for (int mt = 0; mt < 8; ++mt) {
                MMA(Cacc[mt][0], wa[mt][kc][0], wa[mt][kc][1],
                    wa[mt][kc][2], wa[mt][kc][3], rb0, rb1);
                MMA(Cacc[mt][1], wa[mt][kc][0], wa[mt][kc][1],
                    wa[mt][kc][2], wa[mt][kc][3], rb2, rb3);
            }
        }

        // ---- (4) prefetch x(t+2) ----
        if (t + 2 < T_STEPS && lane < NB) {
#pragma unroll
            for (int d = 0; d < NIN; ++d) xv[d] = xr[(t + 2) * NIN + d];
        }

        // ---- (5) packed f16x2 activations + fp32 c update ----
#pragma unroll
        for (int p = 0; p < 2; ++p)
#pragma unroll
            for (int nt = 0; nt < 2; ++nt)
#pragma unroll
                for (int rr = 0; rr < 2; ++rr) {
                    const int j0 = rr * 2, j1 = rr * 2 + 1;
                    __half2 ci = pack2h(Cacc[p][nt][j0],     Cacc[p][nt][j1]);
                    __half2 cf = pack2h(Cacc[2 + p][nt][j0], Cacc[2 + p][nt][j1]);
                    __half2 cg = pack2h(Cacc[4 + p][nt][j0], Cacc[4 + p][nt][j1]);
                    __half2 co = pack2h(Cacc[6 + p][nt][j0], Cacc[6 + p][nt][j1]);
                    __half2 gi = __hfma2(tanh2(__hmul2(ci, h05)), h05, h05);
                    __half2 gf = __hfma2(tanh2(__hmul2(cf, h05)), h05, h05);
                    __half2 gg = tanh2(cg);
                    __half2 go = __hfma2(tanh2(__hmul2(co, h05)), h05, h05);
                    __half2 ig = __hmul2(gi, gg);
                    const int idx = 8 * p + 4 * rr + 2 * nt;
                    float c0 = fmaf(__low2float(gf),  creg[idx],     __low2float(ig));
                    float c1 = fmaf(__high2float(gf), creg[idx + 1], __high2float(ig));
                    creg[idx]     = c0;
                    creg[idx + 1] = c1;
                    __half2 tc = tanh2(pack2h(c0, c1));
                    h2[4 * p + 2 * rr + nt] = __hmul2(go, tc);
                }
    }

    // NOTE: x(t+1) odd-buffer x_lo rows are 6 offset (48..52 hi, 53 one, 54..58 lo)
    // and even-buffer (32..36 hi, 37 one, 38..42 lo) — both match W cols 32..47 pattern.

    // ============ final projection ============
    float acc[4][2];
#pragma unroll
    for (int q = 0; q < 4; ++q) { acc[q][0] = 0.0f; acc[q][1] = 0.0f; }
#pragma unroll
    for (int p = 0; p < 2; ++p)
#pragma unroll
        for (int rr = 0; rr < 2; ++rr) {
            const int u = p * 16 + rr * 8 + gl;
            const float w0 = W_fc[u], w1 = W_fc[H + u];
#pragma unroll
            for (int nt = 0; nt < 2; ++nt) {
                const __half2 hv = h2[4 * p + 2 * rr + nt];
                const float hv0 = __low2float(hv), hv1 = __high2float(hv);
                acc[nt * 2 + 0][0] = fmaf(hv0, w0, acc[nt * 2 + 0][0]);
                acc[nt * 2 + 0][1] = fmaf(hv0, w1, acc[nt * 2 + 0][1]);
                acc[nt * 2 + 1][0] = fmaf(hv1, w0, acc[nt * 2 + 1][0]);
                acc[nt * 2 + 1][1] = fmaf(hv1, w1, acc[nt * 2 + 1][1]);
            }
        }
#pragma unroll
    for (int off = 4; off <= 16; off <<= 1)
#pragma unroll
        for (int q = 0; q < 4; ++q) {
            acc[q][0] += __shfl_xor_sync(0xffffffffu, acc[q][0], off);
            acc[q][1] += __shfl_xor_sync(0xffffffffu, acc[q][1], off);
        }
    if (lane < 4) {
        const float f0 = b_fc[0], f1 = b_fc[1];
#pragma unroll
        for (int nt = 0; nt < 2; ++nt)
#pragma unroll
            for (int e = 0; e < 2; ++e) {
                const int col = nt * 8 + 2 * lane + e;
                out[(wb0 + col) * 2 + 0] = acc[nt * 2 + e][0] + f0;
                out[(wb0 + col) * 2 + 1] = acc[nt * 2 + e][1] + f1;
            }
    }
}

extern "C" void kernel_launch(void* const* d_in, const int* in_sizes, int n_in,
                              void* d_out, int out_size) {
    const float* x    = (const float*)d_in[0];
    const float* W_ih = (const float*)d_in[1];
    const float* W_hh = (const float*)d_in[2];
    const float* b_ih = (const float*)d_in[3];
    const float* b_hh = (const float*)d_in[4];
    const float* W_fc = (const float*)d_in[5];
    const float* b_fc = (const float*)d_in[6];
    float* out = (float*)d_out;

    int B = in_sizes[0] / (T_STEPS * NIN);
    int bpc = WARPS * NB;                      // 64 batches per CTA
    int blocks = (B + bpc - 1) / bpc;
    lstm_xdb_kernel<<<blocks, THREADS>>>(x, W_ih, W_hh, b_ih, b_hh,
                                         W_fc, b_fc, out, B);
}

// round 17
// speedup vs baseline: 1.7939x; 1.0634x over previous
#include <cuda_runtime.h>
#include <cuda_fp16.h>

#define T_STEPS 200
#define NIN     5
#define H       32
#define G4      128          // 4H gate rows
#define NB      16           // batches per warp (2 n-tiles)
#define WARPS   4
#define THREADS (WARPS * 32)

#define WPITCH  56                        // halfs per W row (112 B, LDSM conflict-free)
#define WBYTES  (G4 * WPITCH * 2)         // 14336
#define OFF_H   WBYTES
#define HPITCH  48                        // bytes per Hbuf row
#define HWARPSZ (48 * HPITCH)             // 2304 per warp

struct SmemLayout {
    __half Whi[G4][WPITCH];
    __half Hbuf[WARPS][48][HPITCH / 2];
};

// ---------- PTX helpers ----------
__device__ __forceinline__ unsigned smem_u32(const void* p) {
    unsigned a;
    asm("{ .reg .u64 t; cvta.to.shared.u64 t, %1; cvt.u32.u64 %0, t; }"
        : "=r"(a) : "l"(p));
    return a;
}
__device__ __forceinline__ void ldsm_x4(unsigned& a0, unsigned& a1,
                                        unsigned& a2, unsigned& a3, unsigned addr) {
    asm volatile("ldmatrix.sync.aligned.m8n8.x4.shared.b16 {%0,%1,%2,%3}, [%4];"
                 : "=r"(a0), "=r"(a1), "=r"(a2), "=r"(a3) : "r"(addr));
}
__device__ __forceinline__ void ldsm_x4t(unsigned& b0, unsigned& b1,
                                         unsigned& b2, unsigned& b3, unsigned addr) {
    asm volatile("ldmatrix.sync.aligned.m8n8.x4.trans.shared.b16 {%0,%1,%2,%3}, [%4];"
                 : "=r"(b0), "=r"(b1), "=r"(b2), "=r"(b3) : "r"(addr));
}
#define MMA(Cr, A0, A1, A2, A3, B0, B1)                                        \
    asm volatile("mma.sync.aligned.m16n8k16.row.col.f32.f16.f16.f32 "          \
                 "{%0,%1,%2,%3}, {%4,%5,%6,%7}, {%8,%9}, {%0,%1,%2,%3};"       \
                 : "+f"((Cr)[0]), "+f"((Cr)[1]), "+f"((Cr)[2]), "+f"((Cr)[3])  \
                 : "r"(A0), "r"(A1), "r"(A2), "r"(A3), "r"(B0), "r"(B1))

__device__ __forceinline__ void sts32(unsigned addr, unsigned v) {
    asm volatile("st.shared.b32 [%0], %1;" :: "r"(addr), "r"(v) : "memory");
}
__device__ __forceinline__ void sts16(unsigned addr, unsigned short v) {
    asm volatile("st.shared.b16 [%0], %1;" :: "r"(addr), "h"(v) : "memory");
}

// ---------- packed f16x2 helpers ----------
__device__ __forceinline__ __half2 tanh2(__half2 v) {
    unsigned u = *reinterpret_cast<unsigned*>(&v), r;
    asm("tanh.approx.f16x2 %0, %1;" : "=r"(r) : "r"(u));
    return *reinterpret_cast<__half2*>(&r);
}
__device__ __forceinline__ __half2 pack2h(float e0, float e1) {   // low=e0
    unsigned r;
    asm("cvt.rn.f16x2.f32 %0, %1, %2;" : "=r"(r) : "f"(e1), "f"(e0));
    return *reinterpret_cast<__half2*>(&r);
}
__device__ __forceinline__ unsigned h2bits(__half2 v) {
    return *reinterpret_cast<unsigned*>(&v);
}
__device__ __forceinline__ __half2 bits2h(unsigned u) {
    return *reinterpret_cast<__half2*>(&u);
}

__global__ void __launch_bounds__(THREADS, 2)
lstm_pk_kernel(const float* __restrict__ x,
               const float* __restrict__ W_ih,
               const float* __restrict__ W_hh,
               const float* __restrict__ b_ih,
               const float* __restrict__ b_hh,
               const float* __restrict__ W_fc,
               const float* __restrict__ b_fc,
               float* __restrict__ out, int B) {
    __shared__ __align__(16) SmemLayout sm;

    const int tid  = threadIdx.x;
    const int wid  = tid >> 5;
    const int lane = tid & 31;

    // ============ init: W (fp16, x_lo duplicated cols) ============
    {
        const int g = tid;  // 0..127
        for (int k = 0; k < WPITCH; ++k) {
            float v;
            if (k < H)            v = W_hh[g * H + k];
            else if (k < 37)      v = W_ih[g * NIN + (k - 32)];
            else if (k == 37)     v = b_ih[g] + b_hh[g];
            else if (k >= 38 && k < 43) v = W_ih[g * NIN + (k - 38)]; // x_lo cols
            else                  v = 0.0f;
            sm.Whi[g][k] = __float2half(v);
        }
    }
    {   // zero H buffers
        unsigned* hz = (unsigned*)&sm.Hbuf[0][0][0];
        for (int i = tid; i < (WARPS * HWARPSZ) / 4; i += THREADS) hz[i] = 0u;
    }
    __syncthreads();
    if (tid < WARPS * NB)
        sm.Hbuf[tid / NB][37][tid % NB] = __float2half(1.0f);
    __syncthreads();

    const int wb0 = blockIdx.x * (WARPS * NB) + wid * NB;
    if (wb0 >= B) return;

    const unsigned sbase = smem_u32(&sm);
    const unsigned laneA = (unsigned)((lane & 15) * (WPITCH * 2) + (lane >> 4) * 16);
    const unsigned hwarp = sbase + OFF_H + wid * HWARPSZ;
    const unsigned addrB = hwarp + (unsigned)((lane & 15) * HPITCH + (lane >> 4) * 16);
    const int gl = lane >> 2;
    const int tl = lane & 3;

    // ---- pin W fragments in registers (step-invariant) ----
    unsigned wa[8][3][4];
#pragma unroll
    for (int mt = 0; mt < 8; ++mt)
#pragma unroll
        for (int kc = 0; kc < 3; ++kc)
            ldsm_x4(wa[mt][kc][0], wa[mt][kc][1], wa[mt][kc][2], wa[mt][kc][3],
                    sbase + laneA + (unsigned)(mt * (16 * WPITCH * 2) + kc * 32));

    const float* xr = x + (size_t)(wb0 + lane) * (T_STEPS * NIN);  // lane<16 valid

    float xv[NIN];
    if (lane < NB) {
#pragma unroll
        for (int d = 0; d < NIN; ++d) xv[d] = xr[d];
    }

    // state: c fp32 (16), h packed f16x2 (8): hidx = 4p + 2rr + nt, pair e0/e1
    float creg[16];
    __half2 h2[8];
#pragma unroll
    for (int i = 0; i < 16; ++i) creg[i] = 0.0f;
#pragma unroll
    for (int i = 0; i < 8; ++i) h2[i] = bits2h(0u);

    const __half2 h05 = __float2half2_rn(0.5f);

#pragma unroll 1
    for (int t = 0; t < T_STEPS; ++t) {
        // ---- write h (f16x2 pairs) ----
#pragma unroll
        for (int p = 0; p < 2; ++p)
#pragma unroll
            for (int rr = 0; rr < 2; ++rr) {
                const int u = p * 16 + rr * 8 + gl;
#pragma unroll
                for (int nt = 0; nt < 2; ++nt)
                    sts32(hwarp + (unsigned)(u * HPITCH + (nt * 8 + 2 * tl) * 2),
                          h2bits(h2[4 * p + 2 * rr + nt]));
            }
        // ---- write x rows: hi at 32..36, lo at 38..42 ----
        if (lane < NB) {
#pragma unroll
            for (int d = 0; d < NIN; ++d) {
                __half xh = __float2half(xv[d]);
                __half xl = __float2half(xv[d] - __half2float(xh));
                sts16(hwarp + (unsigned)((32 + d) * HPITCH + lane * 2),
                      *reinterpret_cast<unsigned short*>(&xh));
                sts16(hwarp + (unsigned)((38 + d) * HPITCH + lane * 2),
                      *reinterpret_cast<unsigned short*>(&xl));
            }
        }
        __syncwarp();

        // ---- prefetch next x ----
        if (t + 1 < T_STEPS && lane < NB) {
#pragma unroll
            for (int d = 0; d < NIN; ++d) xv[d] = xr[(t + 1) * NIN + d];
        }

        // ---- single-pass MMA from pinned registers ----
        float Cacc[8][2][4];
#pragma unroll
        for (int m = 0; m < 8; ++m)
#pragma unroll
            for (int n = 0; n < 2; ++n)
#pragma unroll
                for (int e = 0; e < 4; ++e) Cacc[m][n][e] = 0.0f;

#pragma unroll
        for (int kc = 0; kc < 3; ++kc) {
            unsigned rb0, rb1, rb2, rb3;
            ldsm_x4t(rb0, rb1, rb2, rb3, addrB + (unsigned)(kc * 16 * HPITCH));
#pragma unroll
            for (int mt = 0; mt < 8; ++mt) {
                MMA(Cacc[mt][0], wa[mt][kc][0], wa[mt][kc][1],
                    wa[mt][kc][2], wa[mt][kc][3], rb0, rb1);
                MMA(Cacc[mt][1], wa[mt][kc][0], wa[mt][kc][1],
                    wa[mt][kc][2], wa[mt][kc][3], rb2, rb3);
            }
        }

        // ---- packed f16x2 activations + fp32 c update ----
#pragma unroll
        for (int p = 0; p < 2; ++p)
#pragma unroll
            for (int nt = 0; nt < 2; ++nt)
#pragma unroll
                for (int rr = 0; rr < 2; ++rr) {
                    const int j0 = rr * 2, j1 = rr * 2 + 1;
                    __half2 ci = pack2h(Cacc[p][nt][j0],     Cacc[p][nt][j1]);
                    __half2 cf = pack2h(Cacc[2 + p][nt][j0], Cacc[2 + p][nt][j1]);
                    __half2 cg = pack2h(Cacc[4 + p][nt][j0], Cacc[4 + p][nt][j1]);
                    __half2 co = pack2h(Cacc[6 + p][nt][j0], Cacc[6 + p][nt][j1]);
                    __half2 gi = __hfma2(tanh2(__hmul2(ci, h05)), h05, h05);
                    __half2 gf = __hfma2(tanh2(__hmul2(cf, h05)), h05, h05);
                    __half2 gg = tanh2(cg);
                    __half2 go = __hfma2(tanh2(__hmul2(co, h05)), h05, h05);
                    __half2 ig = __hmul2(gi, gg);
                    const int idx = 8 * p + 4 * rr + 2 * nt;
                    float c0 = fmaf(__low2float(gf),  creg[idx],     __low2float(ig));
                    float c1 = fmaf(__high2float(gf), creg[idx + 1], __high2float(ig));
                    creg[idx]     = c0;
                    creg[idx + 1] = c1;
                    __half2 tc = tanh2(pack2h(c0, c1));
                    h2[4 * p + 2 * rr + nt] = __hmul2(go, tc);
                }
    }

    // ============ final projection ============
    float acc[4][2];
#pragma unroll
    for (int q = 0; q < 4; ++q) { acc[q][0] = 0.0f; acc[q][1] = 0.0f; }
#pragma unroll
    for (int p = 0; p < 2; ++p)
#pragma unroll
        for (int rr = 0; rr < 2; ++rr) {
            const int u = p * 16 + rr * 8 + gl;
            const float w0 = W_fc[u], w1 = W_fc[H + u];
#pragma unroll
            for (int nt = 0; nt < 2; ++nt) {
                const __half2 hv = h2[4 * p + 2 * rr + nt];
                const float hv0 = __low2float(hv), hv1 = __high2float(hv);
                acc[nt * 2 + 0][0] = fmaf(hv0, w0, acc[nt * 2 + 0][0]);
                acc[nt * 2 + 0][1] = fmaf(hv0, w1, acc[nt * 2 + 0][1]);
                acc[nt * 2 + 1][0] = fmaf(hv1, w0, acc[nt * 2 + 1][0]);
                acc[nt * 2 + 1][1] = fmaf(hv1, w1, acc[nt * 2 + 1][1]);
            }
        }
#pragma unroll
    for (int off = 4; off <= 16; off <<= 1)
#pragma unroll
        for (int q = 0; q < 4; ++q) {
            acc[q][0] += __shfl_xor_sync(0xffffffffu, acc[q][0], off);
            acc[q][1] += __shfl_xor_sync(0xffffffffu, acc[q][1], off);
        }
    if (lane < 4) {
        const float f0 = b_fc[0], f1 = b_fc[1];
#pragma unroll
        for (int nt = 0; nt < 2; ++nt)
#pragma unroll
            for (int e = 0; e < 2; ++e) {
                const int col = nt * 8 + 2 * lane + e;
                out[(wb0 + col) * 2 + 0] = acc[nt * 2 + e][0] + f0;
                out[(wb0 + col) * 2 + 1] = acc[nt * 2 + e][1] + f1;
            }
    }
}

extern "C" void kernel_launch(void* const* d_in, const int* in_sizes, int n_in,
                              void* d_out, int out_size) {
    const float* x    = (const float*)d_in[0];
    const float* W_ih = (const float*)d_in[1];
    const float* W_hh = (const float*)d_in[2];
    const float* b_ih = (const float*)d_in[3];
    const float* b_hh = (const float*)d_in[4];
    const float* W_fc = (const float*)d_in[5];
    const float* b_fc = (const float*)d_in[6];
    float* out = (float*)d_out;

    int B = in_sizes[0] / (T_STEPS * NIN);
    int bpc = WARPS * NB;                      // 64 batches per CTA
    int blocks = (B + bpc - 1) / bpc;
    lstm_pk_kernel<<<blocks, THREADS>>>(x, W_ih, W_hh, b_ih, b_hh,
                                        W_fc, b_fc, out, B);
}